// round 4
// baseline (speedup 1.0000x reference)
#include <cuda_runtime.h>
#include <math.h>

// ---------------------------------------------------------------------------
// Problem constants
// ---------------------------------------------------------------------------
#define BATCH 4
#define C_DIM 1024
#define CI_DIM 512
#define T_DIM 16
#define H_DIM 28
#define W_DIM 28
#define NPOS (T_DIM * H_DIM * W_DIM)   // 12544
#define TP 8
#define HP 14
#define WP 14
#define MPOS (TP * HP * WP)            // 1568

// ---------------------------------------------------------------------------
// Scratch (device globals; no cudaMalloc allowed)
// ---------------------------------------------------------------------------
__device__ float d_xT[(size_t)BATCH * NPOS * C_DIM];     // x transposed (B,N,C)
__device__ float d_theta[(size_t)BATCH * NPOS * CI_DIM]; // theta (B,N,Ci)
__device__ float d_scr[(size_t)BATCH * NPOS * CI_DIM];   // conv scratch (B,N,Ci)
__device__ float d_phi[(size_t)BATCH * MPOS * CI_DIM];   // phi pooled (B,M,Ci)
__device__ float d_gmc[(size_t)BATCH * MPOS * CI_DIM];   // g pooled (B,M,Ci)
__device__ float d_gcm[(size_t)BATCH * CI_DIM * MPOS];   // g pooled T (B,Ci,M)
__device__ float d_fbuf[(size_t)BATCH * NPOS * MPOS];    // attention logits (B,N,M)
__device__ float d_ybuf[(size_t)BATCH * NPOS * CI_DIM];  // y (B,N,Ci)

// ---------------------------------------------------------------------------
// Tiled transpose: in (R, Cc) -> out (Cc, R), batched over z
// ---------------------------------------------------------------------------
__global__ void transpose_k(const float* __restrict__ in, float* __restrict__ out,
                            int R, int Cc, long sIn, long sOut) {
    __shared__ float tile[32][33];
    const float* inb = in + (long)blockIdx.z * sIn;
    float* outb = out + (long)blockIdx.z * sOut;
    const int c0 = blockIdx.x * 32;
    const int r0 = blockIdx.y * 32;
    const int tx = threadIdx.x, ty = threadIdx.y;
#pragma unroll
    for (int i = 0; i < 32; i += 8)
        tile[ty + i][tx] = inb[(long)(r0 + ty + i) * Cc + c0 + tx];
    __syncthreads();
#pragma unroll
    for (int i = 0; i < 32; i += 8)
        outb[(long)(c0 + ty + i) * R + r0 + tx] = tile[tx][ty + i];
}

// ---------------------------------------------------------------------------
// 2x2x2 max pool: conv (B, NPOS, CI) -> out (B, MPOS, CI)
// ---------------------------------------------------------------------------
__global__ void pool_k(const float* __restrict__ conv, float* __restrict__ out) {
    const int ci = blockIdx.x * 256 + threadIdx.x;
    const int m = blockIdx.y;
    const int b = blockIdx.z;
    const int wp = m % WP;
    const int hp = (m / WP) % HP;
    const int tp = m / (WP * HP);
    const float* cb = conv + (long)b * NPOS * CI_DIM;
    const long n0 = (long)(2 * tp) * (H_DIM * W_DIM) + (long)(2 * hp) * W_DIM + 2 * wp;
    float mx = -INFINITY;
#pragma unroll
    for (int dt = 0; dt < 2; dt++)
#pragma unroll
        for (int dh = 0; dh < 2; dh++)
#pragma unroll
            for (int dw = 0; dw < 2; dw++) {
                long n = n0 + dt * (H_DIM * W_DIM) + dh * W_DIM + dw;
                mx = fmaxf(mx, cb[n * CI_DIM + ci]);
            }
    out[((long)b * MPOS + m) * CI_DIM + ci] = mx;
}

// ---------------------------------------------------------------------------
// Row softmax over MPOS=1568 entries, one block per row (register-resident)
// ---------------------------------------------------------------------------
__global__ void __launch_bounds__(256) softmax_rows(float* __restrict__ f) {
    float* p = f + (long)blockIdx.x * MPOS;
    const int t = threadIdx.x;
    float v[7];
    int cnt = 0;
    float mx = -1e30f;
    for (int i = t; i < MPOS; i += 256) {
        v[cnt] = p[i];
        mx = fmaxf(mx, v[cnt]);
        cnt++;
    }
    __shared__ float sred[8];
#pragma unroll
    for (int o = 16; o; o >>= 1) mx = fmaxf(mx, __shfl_xor_sync(0xffffffffu, mx, o));
    if ((t & 31) == 0) sred[t >> 5] = mx;
    __syncthreads();
    if (t < 32) {
        float m2 = (t < 8) ? sred[t] : -1e30f;
#pragma unroll
        for (int o = 4; o; o >>= 1) m2 = fmaxf(m2, __shfl_xor_sync(0xffffffffu, m2, o));
        if (t == 0) sred[0] = m2;
    }
    __syncthreads();
    mx = sred[0];
    float sum = 0.f;
    for (int j = 0; j < cnt; j++) {
        v[j] = __expf(v[j] - mx);
        sum += v[j];
    }
    __syncthreads();  // protect sred reuse
#pragma unroll
    for (int o = 16; o; o >>= 1) sum += __shfl_xor_sync(0xffffffffu, sum, o);
    if ((t & 31) == 0) sred[t >> 5] = sum;
    __syncthreads();
    if (t < 32) {
        float s2 = (t < 8) ? sred[t] : 0.f;
#pragma unroll
        for (int o = 4; o; o >>= 1) s2 += __shfl_xor_sync(0xffffffffu, s2, o);
        if (t == 0) sred[0] = s2;
    }
    __syncthreads();
    const float inv = 1.0f / sred[0];
    int j = 0;
    for (int i = t; i < MPOS; i += 256) {
        p[i] = v[j] * inv;
        j++;
    }
}

// ---------------------------------------------------------------------------
// NT SGEMM: C(MxN) = A(MxK, row-major) * B(NxK, row-major)^T, batched (z)
// EPI 0: plain    EPI 1: + colBias[col]
// EPI 2: out = resid + gamma[row]*rsqrt(1+eps)*(acc + rowBias[row]) + beta[row]
// Requires M%128==0, N%32==0, K%16==0 (all shapes here satisfy this).
// ---------------------------------------------------------------------------
#define BM 128
#define BN 32
#define BK 16

template <int EPI>
__global__ void __launch_bounds__(256, 2)
gemm_nt(const float* __restrict__ A, const float* __restrict__ B,
        float* __restrict__ C, int M, int N, int K,
        long sA, long sB, long sC,
        const float* __restrict__ colBias,
        const float* __restrict__ rowBias,
        const float* __restrict__ gamma,
        const float* __restrict__ beta,
        const float* __restrict__ resid, long sR) {
    __shared__ float As[BK][BM + 4];
    __shared__ float Bs[BK][BN + 4];
    A += (long)blockIdx.z * sA;
    B += (long)blockIdx.z * sB;
    C += (long)blockIdx.z * sC;
    const int m0 = blockIdx.y * BM;
    const int n0 = blockIdx.x * BN;
    const int tid = threadIdx.x;
    const int ty = tid >> 3;   // 0..31 -> row group
    const int tx = tid & 7;    // 0..7  -> col group
    float acc[4][4] = {};

    for (int k0 = 0; k0 < K; k0 += BK) {
        // load A tile 128x16 (512 float4, 2 per thread), transposed into smem
#pragma unroll
        for (int u = 0; u < 2; u++) {
            int idx = tid + u * 256;
            int r = idx >> 2;
            int kk = (idx & 3) << 2;
            const float4 v = *reinterpret_cast<const float4*>(&A[(long)(m0 + r) * K + k0 + kk]);
            As[kk + 0][r] = v.x; As[kk + 1][r] = v.y;
            As[kk + 2][r] = v.z; As[kk + 3][r] = v.w;
        }
        // load B tile 32x16 (128 float4)
        if (tid < 128) {
            int r = tid >> 2;
            int kk = (tid & 3) << 2;
            const float4 v = *reinterpret_cast<const float4*>(&B[(long)(n0 + r) * K + k0 + kk]);
            Bs[kk + 0][r] = v.x; Bs[kk + 1][r] = v.y;
            Bs[kk + 2][r] = v.z; Bs[kk + 3][r] = v.w;
        }
        __syncthreads();
#pragma unroll
        for (int k = 0; k < BK; k++) {
            const float4 a = *reinterpret_cast<const float4*>(&As[k][ty * 4]);
            const float4 b = *reinterpret_cast<const float4*>(&Bs[k][tx * 4]);
            const float av[4] = {a.x, a.y, a.z, a.w};
            const float bv[4] = {b.x, b.y, b.z, b.w};
#pragma unroll
            for (int i = 0; i < 4; i++)
#pragma unroll
                for (int j = 0; j < 4; j++) acc[i][j] += av[i] * bv[j];
        }
        __syncthreads();
    }

    const int row = m0 + ty * 4;
    const int col = n0 + tx * 4;
    if (EPI == 0) {
#pragma unroll
        for (int i = 0; i < 4; i++) {
            float4 v = make_float4(acc[i][0], acc[i][1], acc[i][2], acc[i][3]);
            *reinterpret_cast<float4*>(&C[(long)(row + i) * N + col]) = v;
        }
    } else if (EPI == 1) {
        const float4 cb = *reinterpret_cast<const float4*>(&colBias[col]);
#pragma unroll
        for (int i = 0; i < 4; i++) {
            float4 v = make_float4(acc[i][0] + cb.x, acc[i][1] + cb.y,
                                   acc[i][2] + cb.z, acc[i][3] + cb.w);
            *reinterpret_cast<float4*>(&C[(long)(row + i) * N + col]) = v;
        }
    } else {
        const float rs = rsqrtf(1.0f + 1e-5f);
        const float* rb = resid + (long)blockIdx.z * sR;
#pragma unroll
        for (int i = 0; i < 4; i++) {
            const float s = gamma[row + i] * rs;
            const float wb = rowBias[row + i];
            const float bt = beta[row + i];
            const float4 x4 = *reinterpret_cast<const float4*>(&rb[(long)(row + i) * N + col]);
            float4 v;
            v.x = x4.x + s * (acc[i][0] + wb) + bt;
            v.y = x4.y + s * (acc[i][1] + wb) + bt;
            v.z = x4.z + s * (acc[i][2] + wb) + bt;
            v.w = x4.w + s * (acc[i][3] + wb) + bt;
            *reinterpret_cast<float4*>(&C[(long)(row + i) * N + col]) = v;
        }
    }
}

// ---------------------------------------------------------------------------
// Launch
// ---------------------------------------------------------------------------
extern "C" void kernel_launch(void* const* d_in, const int* in_sizes, int n_in,
                              void* d_out, int out_size) {
    (void)in_sizes; (void)n_in; (void)out_size;
    const float* x     = (const float*)d_in[0];
    const float* g_w   = (const float*)d_in[1];
    const float* g_b   = (const float*)d_in[2];
    const float* th_w  = (const float*)d_in[3];
    const float* th_b  = (const float*)d_in[4];
    const float* ph_w  = (const float*)d_in[5];
    const float* ph_b  = (const float*)d_in[6];
    const float* w_w   = (const float*)d_in[7];
    const float* w_b   = (const float*)d_in[8];
    const float* gamma = (const float*)d_in[9];
    const float* beta  = (const float*)d_in[10];
    float* out = (float*)d_out;

    float *xT, *theta, *scr, *phi, *gmc, *gcm, *fbuf, *ybuf;
    cudaGetSymbolAddress((void**)&xT, d_xT);
    cudaGetSymbolAddress((void**)&theta, d_theta);
    cudaGetSymbolAddress((void**)&scr, d_scr);
    cudaGetSymbolAddress((void**)&phi, d_phi);
    cudaGetSymbolAddress((void**)&gmc, d_gmc);
    cudaGetSymbolAddress((void**)&gcm, d_gcm);
    cudaGetSymbolAddress((void**)&fbuf, d_fbuf);
    cudaGetSymbolAddress((void**)&ybuf, d_ybuf);

    const long sX  = (long)C_DIM * NPOS;
    const long sXT = (long)NPOS * C_DIM;
    const long sTH = (long)NPOS * CI_DIM;
    const long sPH = (long)MPOS * CI_DIM;
    const long sF  = (long)NPOS * MPOS;

    // 1) transpose x: (C, NPOS) -> (NPOS, C) per batch
    transpose_k<<<dim3(NPOS / 32, C_DIM / 32, BATCH), dim3(32, 8)>>>(
        x, xT, C_DIM, NPOS, sX, sXT);

    const dim3 gConv(CI_DIM / BN, NPOS / BM, BATCH);

    // 2) theta conv -> d_theta (N, Ci)
    gemm_nt<1><<<gConv, 256>>>(xT, th_w, theta, NPOS, CI_DIM, C_DIM,
                               sXT, 0, sTH, th_b, nullptr, nullptr, nullptr, nullptr, 0);
    // 3) g conv -> scratch, pool -> (M,Ci), transpose -> (Ci,M)
    gemm_nt<1><<<gConv, 256>>>(xT, g_w, scr, NPOS, CI_DIM, C_DIM,
                               sXT, 0, sTH, g_b, nullptr, nullptr, nullptr, nullptr, 0);
    pool_k<<<dim3(CI_DIM / 256, MPOS, BATCH), 256>>>(scr, gmc);
    transpose_k<<<dim3(CI_DIM / 32, MPOS / 32, BATCH), dim3(32, 8)>>>(
        gmc, gcm, MPOS, CI_DIM, sPH, sPH);
    // 4) phi conv -> scratch, pool -> (M,Ci)
    gemm_nt<1><<<gConv, 256>>>(xT, ph_w, scr, NPOS, CI_DIM, C_DIM,
                               sXT, 0, sTH, ph_b, nullptr, nullptr, nullptr, nullptr, 0);
    pool_k<<<dim3(CI_DIM / 256, MPOS, BATCH), 256>>>(scr, phi);

    // 5) f = theta @ phi^T : (N,Ci)x(M,Ci) -> (N,M)
    gemm_nt<0><<<dim3(MPOS / BN, NPOS / BM, BATCH), 256>>>(
        theta, phi, fbuf, NPOS, MPOS, CI_DIM,
        sTH, sPH, sF, nullptr, nullptr, nullptr, nullptr, nullptr, 0);

    // 6) row softmax over M
    softmax_rows<<<BATCH * NPOS, 256>>>(fbuf);

    // 7) y = f @ g : (N,M)x(Ci,M)^T -> (N,Ci)
    gemm_nt<0><<<dim3(CI_DIM / BN, NPOS / BM, BATCH), 256>>>(
        fbuf, gcm, ybuf, NPOS, CI_DIM, MPOS,
        sF, sPH, sTH, nullptr, nullptr, nullptr, nullptr, nullptr, 0);

    // 8) W conv + BN + residual: out(C,N) = x + scale*(w_w @ y^T + w_b) + beta
    gemm_nt<2><<<dim3(NPOS / BN, C_DIM / BM, BATCH), 256>>>(
        w_w, ybuf, out, C_DIM, NPOS, CI_DIM,
        0, sTH, sX, nullptr, w_b, gamma, beta, x, sX);
}

// round 5
// speedup vs baseline: 1.0574x; 1.0574x over previous
#include <cuda_runtime.h>
#include <math.h>

// ---------------------------------------------------------------------------
// Problem constants
// ---------------------------------------------------------------------------
#define BATCH 4
#define C_DIM 1024
#define CI_DIM 512
#define T_DIM 16
#define H_DIM 28
#define W_DIM 28
#define NPOS (T_DIM * H_DIM * W_DIM)   // 12544
#define TP 8
#define HP 14
#define WP 14
#define MPOS (TP * HP * WP)            // 1568

// ---------------------------------------------------------------------------
// Scratch (device globals; no cudaMalloc allowed)
// ---------------------------------------------------------------------------
__device__ float d_xT[(size_t)BATCH * NPOS * C_DIM];     // x transposed (B,N,C)
__device__ float d_theta[(size_t)BATCH * NPOS * CI_DIM]; // theta (B,N,Ci)
__device__ float d_scr[(size_t)BATCH * NPOS * CI_DIM];   // conv scratch (B,N,Ci)
__device__ float d_phi[(size_t)BATCH * MPOS * CI_DIM];   // phi pooled (B,M,Ci)
__device__ float d_gmc[(size_t)BATCH * MPOS * CI_DIM];   // g pooled (B,M,Ci)
__device__ float d_gcm[(size_t)BATCH * CI_DIM * MPOS];   // g pooled T (B,Ci,M)
__device__ float d_fbuf[(size_t)BATCH * NPOS * MPOS];    // attention logits (B,N,M)
__device__ float d_ybuf[(size_t)BATCH * NPOS * CI_DIM];  // y (B,N,Ci)

// ---------------------------------------------------------------------------
// Tiled transpose: in (R, Cc) -> out (Cc, R), batched over z
// ---------------------------------------------------------------------------
__global__ void transpose_k(const float* __restrict__ in, float* __restrict__ out,
                            int R, int Cc, long sIn, long sOut) {
    __shared__ float tile[32][33];
    const float* inb = in + (long)blockIdx.z * sIn;
    float* outb = out + (long)blockIdx.z * sOut;
    const int c0 = blockIdx.x * 32;
    const int r0 = blockIdx.y * 32;
    const int tx = threadIdx.x, ty = threadIdx.y;
#pragma unroll
    for (int i = 0; i < 32; i += 8)
        tile[ty + i][tx] = inb[(long)(r0 + ty + i) * Cc + c0 + tx];
    __syncthreads();
#pragma unroll
    for (int i = 0; i < 32; i += 8)
        outb[(long)(c0 + ty + i) * R + r0 + tx] = tile[tx][ty + i];
}

// ---------------------------------------------------------------------------
// 2x2x2 max pool: conv (B, NPOS, CI) -> out (B, MPOS, CI)
// ---------------------------------------------------------------------------
__global__ void pool_k(const float* __restrict__ conv, float* __restrict__ out) {
    const int ci = blockIdx.x * 256 + threadIdx.x;
    const int m = blockIdx.y;
    const int b = blockIdx.z;
    const int wp = m % WP;
    const int hp = (m / WP) % HP;
    const int tp = m / (WP * HP);
    const float* cb = conv + (long)b * NPOS * CI_DIM;
    const long n0 = (long)(2 * tp) * (H_DIM * W_DIM) + (long)(2 * hp) * W_DIM + 2 * wp;
    float mx = -INFINITY;
#pragma unroll
    for (int dt = 0; dt < 2; dt++)
#pragma unroll
        for (int dh = 0; dh < 2; dh++)
#pragma unroll
            for (int dw = 0; dw < 2; dw++) {
                long n = n0 + dt * (H_DIM * W_DIM) + dh * W_DIM + dw;
                mx = fmaxf(mx, cb[n * CI_DIM + ci]);
            }
    out[((long)b * MPOS + m) * CI_DIM + ci] = mx;
}

// ---------------------------------------------------------------------------
// Row softmax over MPOS=1568 entries, one block per row (register-resident)
// ---------------------------------------------------------------------------
__global__ void __launch_bounds__(256) softmax_rows(float* __restrict__ f) {
    float* p = f + (long)blockIdx.x * MPOS;
    const int t = threadIdx.x;
    float v[7];
    int cnt = 0;
    float mx = -1e30f;
    for (int i = t; i < MPOS; i += 256) {
        v[cnt] = p[i];
        mx = fmaxf(mx, v[cnt]);
        cnt++;
    }
    __shared__ float sred[8];
#pragma unroll
    for (int o = 16; o; o >>= 1) mx = fmaxf(mx, __shfl_xor_sync(0xffffffffu, mx, o));
    if ((t & 31) == 0) sred[t >> 5] = mx;
    __syncthreads();
    if (t < 32) {
        float m2 = (t < 8) ? sred[t] : -1e30f;
#pragma unroll
        for (int o = 4; o; o >>= 1) m2 = fmaxf(m2, __shfl_xor_sync(0xffffffffu, m2, o));
        if (t == 0) sred[0] = m2;
    }
    __syncthreads();
    mx = sred[0];
    float sum = 0.f;
    for (int j = 0; j < cnt; j++) {
        v[j] = __expf(v[j] - mx);
        sum += v[j];
    }
    __syncthreads();  // protect sred reuse
#pragma unroll
    for (int o = 16; o; o >>= 1) sum += __shfl_xor_sync(0xffffffffu, sum, o);
    if ((t & 31) == 0) sred[t >> 5] = sum;
    __syncthreads();
    if (t < 32) {
        float s2 = (t < 8) ? sred[t] : 0.f;
#pragma unroll
        for (int o = 4; o; o >>= 1) s2 += __shfl_xor_sync(0xffffffffu, s2, o);
        if (t == 0) sred[0] = s2;
    }
    __syncthreads();
    const float inv = 1.0f / sred[0];
    int j = 0;
    for (int i = t; i < MPOS; i += 256) {
        p[i] = v[j] * inv;
        j++;
    }
}

// ---------------------------------------------------------------------------
// NT SGEMM: C(MxN) = A(MxK, row-major) * B(NxK, row-major)^T, batched (z)
// EPI 0: plain    EPI 1: + colBias[col]
// EPI 2: out = resid + gamma[row]*rsqrt(1+eps)*(acc + rowBias[row]) + beta[row]
// Requires M%128==0, N%32==0, K%16==0 (all shapes here satisfy this).
// ---------------------------------------------------------------------------
#define BM 128
#define BN 32
#define BK 16

template <int EPI>
__global__ void __launch_bounds__(256, 2)
gemm_nt(const float* __restrict__ A, const float* __restrict__ B,
        float* __restrict__ C, int M, int N, int K,
        long sA, long sB, long sC,
        const float* __restrict__ colBias,
        const float* __restrict__ rowBias,
        const float* __restrict__ gamma,
        const float* __restrict__ beta,
        const float* __restrict__ resid, long sR) {
    __shared__ float As[BK][BM + 4];
    __shared__ float Bs[BK][BN + 4];
    A += (long)blockIdx.z * sA;
    B += (long)blockIdx.z * sB;
    C += (long)blockIdx.z * sC;
    const int m0 = blockIdx.y * BM;
    const int n0 = blockIdx.x * BN;
    const int tid = threadIdx.x;
    const int ty = tid >> 3;   // 0..31 -> row group
    const int tx = tid & 7;    // 0..7  -> col group
    float acc[4][4] = {};

    for (int k0 = 0; k0 < K; k0 += BK) {
        // load A tile 128x16 (512 float4, 2 per thread), transposed into smem
#pragma unroll
        for (int u = 0; u < 2; u++) {
            int idx = tid + u * 256;
            int r = idx >> 2;
            int kk = (idx & 3) << 2;
            const float4 v = *reinterpret_cast<const float4*>(&A[(long)(m0 + r) * K + k0 + kk]);
            As[kk + 0][r] = v.x; As[kk + 1][r] = v.y;
            As[kk + 2][r] = v.z; As[kk + 3][r] = v.w;
        }
        // load B tile 32x16 (128 float4)
        if (tid < 128) {
            int r = tid >> 2;
            int kk = (tid & 3) << 2;
            const float4 v = *reinterpret_cast<const float4*>(&B[(long)(n0 + r) * K + k0 + kk]);
            Bs[kk + 0][r] = v.x; Bs[kk + 1][r] = v.y;
            Bs[kk + 2][r] = v.z; Bs[kk + 3][r] = v.w;
        }
        __syncthreads();
#pragma unroll
        for (int k = 0; k < BK; k++) {
            const float4 a = *reinterpret_cast<const float4*>(&As[k][ty * 4]);
            const float4 b = *reinterpret_cast<const float4*>(&Bs[k][tx * 4]);
            const float av[4] = {a.x, a.y, a.z, a.w};
            const float bv[4] = {b.x, b.y, b.z, b.w};
#pragma unroll
            for (int i = 0; i < 4; i++)
#pragma unroll
                for (int j = 0; j < 4; j++) acc[i][j] += av[i] * bv[j];
        }
        __syncthreads();
    }

    const int row = m0 + ty * 4;
    const int col = n0 + tx * 4;
    if (EPI == 0) {
#pragma unroll
        for (int i = 0; i < 4; i++) {
            float4 v = make_float4(acc[i][0], acc[i][1], acc[i][2], acc[i][3]);
            *reinterpret_cast<float4*>(&C[(long)(row + i) * N + col]) = v;
        }
    } else if (EPI == 1) {
        const float4 cb = *reinterpret_cast<const float4*>(&colBias[col]);
#pragma unroll
        for (int i = 0; i < 4; i++) {
            float4 v = make_float4(acc[i][0] + cb.x, acc[i][1] + cb.y,
                                   acc[i][2] + cb.z, acc[i][3] + cb.w);
            *reinterpret_cast<float4*>(&C[(long)(row + i) * N + col]) = v;
        }
    } else {
        const float rs = rsqrtf(1.0f + 1e-5f);
        const float* rb = resid + (long)blockIdx.z * sR;
#pragma unroll
        for (int i = 0; i < 4; i++) {
            const float s = gamma[row + i] * rs;
            const float wb = rowBias[row + i];
            const float bt = beta[row + i];
            const float4 x4 = *reinterpret_cast<const float4*>(&rb[(long)(row + i) * N + col]);
            float4 v;
            v.x = x4.x + s * (acc[i][0] + wb) + bt;
            v.y = x4.y + s * (acc[i][1] + wb) + bt;
            v.z = x4.z + s * (acc[i][2] + wb) + bt;
            v.w = x4.w + s * (acc[i][3] + wb) + bt;
            *reinterpret_cast<float4*>(&C[(long)(row + i) * N + col]) = v;
        }
    }
}

// ---------------------------------------------------------------------------
// Launch
// ---------------------------------------------------------------------------
extern "C" void kernel_launch(void* const* d_in, const int* in_sizes, int n_in,
                              void* d_out, int out_size) {
    (void)in_sizes; (void)n_in; (void)out_size;
    const float* x     = (const float*)d_in[0];
    const float* g_w   = (const float*)d_in[1];
    const float* g_b   = (const float*)d_in[2];
    const float* th_w  = (const float*)d_in[3];
    const float* th_b  = (const float*)d_in[4];
    const float* ph_w  = (const float*)d_in[5];
    const float* ph_b  = (const float*)d_in[6];
    const float* w_w   = (const float*)d_in[7];
    const float* w_b   = (const float*)d_in[8];
    const float* gamma = (const float*)d_in[9];
    const float* beta  = (const float*)d_in[10];
    float* out = (float*)d_out;

    float *xT, *theta, *scr, *phi, *gmc, *gcm, *fbuf, *ybuf;
    cudaGetSymbolAddress((void**)&xT, d_xT);
    cudaGetSymbolAddress((void**)&theta, d_theta);
    cudaGetSymbolAddress((void**)&scr, d_scr);
    cudaGetSymbolAddress((void**)&phi, d_phi);
    cudaGetSymbolAddress((void**)&gmc, d_gmc);
    cudaGetSymbolAddress((void**)&gcm, d_gcm);
    cudaGetSymbolAddress((void**)&fbuf, d_fbuf);
    cudaGetSymbolAddress((void**)&ybuf, d_ybuf);

    const long sX  = (long)C_DIM * NPOS;
    const long sXT = (long)NPOS * C_DIM;
    const long sTH = (long)NPOS * CI_DIM;
    const long sPH = (long)MPOS * CI_DIM;
    const long sF  = (long)NPOS * MPOS;

    // 1) transpose x: (C, NPOS) -> (NPOS, C) per batch
    transpose_k<<<dim3(NPOS / 32, C_DIM / 32, BATCH), dim3(32, 8)>>>(
        x, xT, C_DIM, NPOS, sX, sXT);

    const dim3 gConv(CI_DIM / BN, NPOS / BM, BATCH);

    // 2) theta conv -> d_theta (N, Ci)
    gemm_nt<1><<<gConv, 256>>>(xT, th_w, theta, NPOS, CI_DIM, C_DIM,
                               sXT, 0, sTH, th_b, nullptr, nullptr, nullptr, nullptr, 0);
    // 3) g conv -> scratch, pool -> (M,Ci), transpose -> (Ci,M)
    gemm_nt<1><<<gConv, 256>>>(xT, g_w, scr, NPOS, CI_DIM, C_DIM,
                               sXT, 0, sTH, g_b, nullptr, nullptr, nullptr, nullptr, 0);
    pool_k<<<dim3(CI_DIM / 256, MPOS, BATCH), 256>>>(scr, gmc);
    transpose_k<<<dim3(CI_DIM / 32, MPOS / 32, BATCH), dim3(32, 8)>>>(
        gmc, gcm, MPOS, CI_DIM, sPH, sPH);
    // 4) phi conv -> scratch, pool -> (M,Ci)
    gemm_nt<1><<<gConv, 256>>>(xT, ph_w, scr, NPOS, CI_DIM, C_DIM,
                               sXT, 0, sTH, ph_b, nullptr, nullptr, nullptr, nullptr, 0);
    pool_k<<<dim3(CI_DIM / 256, MPOS, BATCH), 256>>>(scr, phi);

    // 5) f = theta @ phi^T : (N,Ci)x(M,Ci) -> (N,M)
    gemm_nt<0><<<dim3(MPOS / BN, NPOS / BM, BATCH), 256>>>(
        theta, phi, fbuf, NPOS, MPOS, CI_DIM,
        sTH, sPH, sF, nullptr, nullptr, nullptr, nullptr, nullptr, 0);

    // 6) row softmax over M
    softmax_rows<<<BATCH * NPOS, 256>>>(fbuf);

    // 7) y = f @ g : (N,M)x(Ci,M)^T -> (N,Ci)
    gemm_nt<0><<<dim3(CI_DIM / BN, NPOS / BM, BATCH), 256>>>(
        fbuf, gcm, ybuf, NPOS, CI_DIM, MPOS,
        sF, sPH, sTH, nullptr, nullptr, nullptr, nullptr, nullptr, 0);

    // 8) W conv + BN + residual: out(C,N) = x + scale*(w_w @ y^T + w_b) + beta
    gemm_nt<2><<<dim3(NPOS / BN, C_DIM / BM, BATCH), 256>>>(
        w_w, ybuf, out, C_DIM, NPOS, CI_DIM,
        0, sTH, sX, nullptr, w_b, gamma, beta, x, sX);
}